// round 10
// baseline (speedup 1.0000x reference)
#include <cuda_runtime.h>
#include <cuda_fp16.h>

#define NN   65536
#define PP   1024
#define BB   64
#define HH   32
#define DIN  16
#define EE   2097152

#define BCTA   512
#define BEDGE  (EE / BCTA)
#define BINCAP 128
#define GSTRIDE 36864              // per-graph edge-bin capacity
#define HSTRIDE 18432              // per-half CSR capacity (ushorts)

// ---------------- device scratch ----------------
__device__ int            d_gcur[BB];
__device__ __align__(16) int d_binE[BB * GSTRIDE];
__device__ __align__(16) unsigned short d_csrU[128 * HSTRIDE];
__device__ __align__(16) int d_rpH[128 * 513];
__device__ __align__(16) __half d_Gh [NN * HH];
__device__ __align__(16) __half d_G2h[NN * HH];
__device__ __align__(16) float d_pool[BB * HH];

__device__ __forceinline__ float ftanh(float x) {
    float e = __expf(2.0f * x);
    return 1.0f - __fdividef(2.0f, e + 1.0f);
}

__device__ __forceinline__ void addRow8(float* acc, uint4 v) {
    float2 f;
    f = __half22float2(*reinterpret_cast<__half2*>(&v.x)); acc[0] += f.x; acc[1] += f.y;
    f = __half22float2(*reinterpret_cast<__half2*>(&v.y)); acc[2] += f.x; acc[3] += f.y;
    f = __half22float2(*reinterpret_cast<__half2*>(&v.z)); acc[4] += f.x; acc[5] += f.y;
    f = __half22float2(*reinterpret_cast<__half2*>(&v.w)); acc[6] += f.x; acc[7] += f.y;
}

// ---------------- zero ----------------
__global__ void k_z() {
    int t = threadIdx.x;
    if (t < BB) d_gcur[t] = 0;
    for (int i = t; i < BB * HH; i += 1024) d_pool[i] = 0.0f;
}

// ---------------- one-pass binning ----------------
__global__ void k_bin(const int* __restrict__ src, const int* __restrict__ dst) {
    __shared__ int bins[BB][BINCAP];
    __shared__ int cur[BB];
    __shared__ int gbase[BB];
    int t = threadIdx.x;
    if (t < BB) cur[t] = 0;
    __syncthreads();
    int base = blockIdx.x * BEDGE;
    for (int i = t; i < BEDGE; i += 256) {
        int s = src[base + i], d = dst[base + i];
        int g = d >> 10;
        int pk = ((d & 1023) << 10) | (s & 1023);
        int p = atomicAdd(&cur[g], 1);
        if (p < BINCAP) bins[g][p] = pk;
        else {
            int q = atomicAdd(&d_gcur[g], 1);
            d_binE[g * GSTRIDE + q] = pk;
        }
    }
    __syncthreads();
    if (t < BB) {
        int m = cur[t]; if (m > BINCAP) m = BINCAP;
        gbase[t] = atomicAdd(&d_gcur[t], m);
    }
    __syncthreads();
    int w = t >> 5, lane = t & 31;
    for (int g = w; g < BB; g += 8) {
        int m = cur[g]; if (m > BINCAP) m = BINCAP;
        int gb = g * GSTRIDE + gbase[g];
        for (int i = lane; i < m; i += 32)
            d_binE[gb + i] = bins[g][i];
    }
}

// ---------------- A: per-half local CSR build + fp16 message compute ----------------
__global__ void __launch_bounds__(512) k_A(const float* __restrict__ x,
                                           const float* __restrict__ W1) {
    extern __shared__ int smA[];
    int* sE    = smA;                                 // GSTRIDE ints
    int* sCnt  = sE + GSTRIDE;                        // 512
    int* sRow  = sCnt + 512;                          // 513 (+3)
    unsigned short* sCsrU = (unsigned short*)(sRow + 516);   // HSTRIDE ushorts
    float* sW  = (float*)(sCsrU + HSTRIDE);           // 16x32 transposed W1

    int t = threadIdx.x;
    int g = blockIdx.x >> 1, h = blockIdx.x & 1;
    int tot = d_gcur[g];

    const int* bin = d_binE + g * GSTRIDE;
    for (int i = t; i < tot; i += 512) sE[i] = bin[i];
    if (t < 512) sCnt[t] = 0;
    for (int i = t; i < HH * DIN; i += 512)
        sW[(i & 15) * HH + (i >> 4)] = W1[i];
    __syncthreads();

    for (int i = t; i < tot; i += 512) {
        int e = sE[i]; int dl = e >> 10;
        if ((dl >> 9) == h) atomicAdd(&sCnt[dl & 511], 1);
    }
    __syncthreads();
    if (t < 32) {
        int loc[16]; int s = 0;
#pragma unroll
        for (int i = 0; i < 16; i++) { loc[i] = sCnt[t * 16 + i]; s += loc[i]; }
        int run = s;
#pragma unroll
        for (int off = 1; off < 32; off <<= 1) {
            int v = __shfl_up_sync(0xffffffffu, run, off);
            if (t >= off) run += v;
        }
        int excl = run - s;
#pragma unroll
        for (int i = 0; i < 16; i++) { sRow[t * 16 + i] = excl; excl += loc[i]; }
        if (t == 31) sRow[512] = excl;
    }
    __syncthreads();
    if (t < 512) sCnt[t] = sRow[t];
    __syncthreads();
    for (int i = t; i < tot; i += 512) {
        int e = sE[i]; int dl = e >> 10;
        if ((dl >> 9) == h) {
            int p = atomicAdd(&sCnt[dl & 511], 1);
            sCsrU[p] = (unsigned short)(e & 1023);
        }
    }
    __syncthreads();

    int half = blockIdx.x;
    int m = sRow[512];
    unsigned int* gcsr = (unsigned int*)(d_csrU + (size_t)half * HSTRIDE);
    const unsigned int* scsr = (const unsigned int*)sCsrU;
    for (int i = t; i < (m + 1) / 2; i += 512) gcsr[i] = scsr[i];
    for (int i = t; i < 513; i += 512) d_rpH[half * 513 + i] = sRow[i];

    // messages: G[node] = (x[node] @ W1^T) * dis  -> fp16
    {
        int nl = t;
        int node = g * PP + (h << 9) + nl;
        float xv[DIN];
        const float4* xp = (const float4*)(x + (size_t)node * DIN);
#pragma unroll
        for (int i = 0; i < DIN / 4; i++) {
            float4 v = xp[i];
            xv[4*i] = v.x; xv[4*i+1] = v.y; xv[4*i+2] = v.z; xv[4*i+3] = v.w;
        }
        float dis = rsqrtf((float)(sRow[nl + 1] - sRow[nl]) + 1.0f);
        float4 a[8];
#pragma unroll
        for (int q = 0; q < 8; q++) a[q] = make_float4(0.f, 0.f, 0.f, 0.f);
        const float4* sW4 = (const float4*)sW;
#pragma unroll
        for (int ii = 0; ii < DIN; ii++) {
            float xi = xv[ii];
#pragma unroll
            for (int q = 0; q < 8; q++) {
                float4 w = sW4[ii * 8 + q];
                a[q].x = fmaf(xi, w.x, a[q].x);
                a[q].y = fmaf(xi, w.y, a[q].y);
                a[q].z = fmaf(xi, w.z, a[q].z);
                a[q].w = fmaf(xi, w.w, a[q].w);
            }
        }
        __half2 hh[16];
#pragma unroll
        for (int q = 0; q < 8; q++) {
            hh[2*q]   = __floats2half2_rn(a[q].x * dis, a[q].y * dis);
            hh[2*q+1] = __floats2half2_rn(a[q].z * dis, a[q].w * dis);
        }
        uint4* gp = (uint4*)(d_Gh + (size_t)node * HH);
        const uint4* hp = (const uint4*)hh;
#pragma unroll
        for (int q = 0; q < 4; q++) gp[q] = hp[q];
    }
}

// ---------------- fp16 smem gather core ----------------
// lane: c = lane&3 (16B chunk of 64B row), grp = lane>>2 (8 edge groups)
__device__ __forceinline__ void gatherNodeH(float* acc, const uint4* g4,
                                            const unsigned short* sCsr,
                                            int start, int end, int nodeRow,
                                            int grp, int c) {
#pragma unroll
    for (int j = 0; j < 8; j++) acc[j] = 0.0f;
    int b = start;
    for (; b + 32 <= end; b += 32) {
#pragma unroll
        for (int i = 0; i < 4; i++) {
            int s = (int)sCsr[b + i * 8 + grp];
            addRow8(acc, g4[s * 4 + c]);
        }
    }
    for (int j = b + grp; j < end; j += 8) {
        int s = (int)sCsr[j];
        addRow8(acc, g4[s * 4 + c]);
    }
#pragma unroll
    for (int d = 4; d <= 16; d <<= 1) {
#pragma unroll
        for (int j = 0; j < 8; j++)
            acc[j] += __shfl_xor_sync(0xffffffffu, acc[j], d);
    }
    addRow8(acc, g4[nodeRow * 4 + c]);      // self loop, once, after combine
}

// ---------------- B: layer-1 gather + W2 transform ----------------
__global__ void __launch_bounds__(1024) k_B(const float* __restrict__ b1,
                                            const float* __restrict__ W2) {
    extern __shared__ char smB[];
    __half* sGh = (__half*)smB;                        // 64KB
    int*    sRp = (int*)(smB + PP * HH * 2);           // 513 (+3)
    unsigned short* sCsr = (unsigned short*)(smB + PP * HH * 2 + 516 * 4);
    int t = threadIdx.x;
    int g = blockIdx.x >> 1, h = blockIdx.x & 1, half = blockIdx.x;

    const uint4* gs = (const uint4*)(d_Gh + (size_t)g * PP * HH);
    uint4* sg4 = (uint4*)sGh;
    for (int i = t; i < PP * HH / 8; i += 1024) sg4[i] = gs[i];
    for (int i = t; i < 513; i += 1024) sRp[i] = d_rpH[half * 513 + i];
    __syncthreads();
    int m = sRp[512];
    const unsigned int* gcsr = (const unsigned int*)(d_csrU + (size_t)half * HSTRIDE);
    unsigned int* scsr = (unsigned int*)sCsr;
    for (int i = t; i < (m + 1) / 2; i += 1024) scsr[i] = gcsr[i];

    int lane = t & 31, w = t >> 5;
    int c = lane & 3, grp = lane >> 2;
    float4 wr[8];
    const float4* w4 = (const float4*)(W2 + lane * HH);
#pragma unroll
    for (int q = 0; q < 8; q++) wr[q] = w4[q];         // W2 row `lane`
    float bv[8];
    {
        float4 ba = *(const float4*)(b1 + 8 * c);
        float4 bb = *(const float4*)(b1 + 8 * c + 4);
        bv[0]=ba.x; bv[1]=ba.y; bv[2]=ba.z; bv[3]=ba.w;
        bv[4]=bb.x; bv[5]=bb.y; bv[6]=bb.z; bv[7]=bb.w;
    }
    __syncthreads();

    const uint4* g4 = (const uint4*)sGh;
    for (int nl = w * 16; nl < w * 16 + 16; nl++) {
        int start = sRp[nl], end = sRp[nl + 1];
        float dis = rsqrtf((float)(end - start) + 1.0f);
        int nodeRow = (h << 9) + nl;
        float acc[8];
        gatherNodeH(acc, g4, sCsr, start, end, nodeRow, grp, c);
        float tv[8];
#pragma unroll
        for (int j = 0; j < 8; j++) tv[j] = ftanh(fmaf(dis, acc[j], bv[j]));
        float o = 0.0f;
#pragma unroll
        for (int k = 0; k < HH; k++) {
            float tk = __shfl_sync(0xffffffffu, tv[k & 7], k >> 3);
            o = fmaf(tk, ((const float*)wr)[k], o);
        }
        // write G2 fp16 packed
        float od = o * dis;
        float odn = __shfl_down_sync(0xffffffffu, od, 1);
        if (!(lane & 1)) {
            __half2 hv = __floats2half2_rn(od, odn);
            int gnode = g * PP + nodeRow;
            ((__half2*)d_G2h)[(size_t)gnode * 16 + (lane >> 1)] = hv;
        }
    }
}

// ---------------- C: layer-2 gather + Wl transform + pool ----------------
__global__ void __launch_bounds__(1024) k_C(const float* __restrict__ b2,
                                            const float* __restrict__ Wl,
                                            const float* __restrict__ bl) {
    extern __shared__ char smC[];
    __half* sGh = (__half*)smC;
    int*    sRp = (int*)(smC + PP * HH * 2);
    unsigned short* sCsr = (unsigned short*)(smC + PP * HH * 2 + 516 * 4);
    float*  sRed = (float*)(smC + PP * HH * 2 + 516 * 4 + HSTRIDE * 2);
    int t = threadIdx.x;
    int g = blockIdx.x >> 1, h = blockIdx.x & 1, half = blockIdx.x;

    const uint4* gs = (const uint4*)(d_G2h + (size_t)g * PP * HH);
    uint4* sg4 = (uint4*)sGh;
    for (int i = t; i < PP * HH / 8; i += 1024) sg4[i] = gs[i];
    for (int i = t; i < 513; i += 1024) sRp[i] = d_rpH[half * 513 + i];
    __syncthreads();
    int m = sRp[512];
    const unsigned int* gcsr = (const unsigned int*)(d_csrU + (size_t)half * HSTRIDE);
    unsigned int* scsr = (unsigned int*)sCsr;
    for (int i = t; i < (m + 1) / 2; i += 1024) scsr[i] = gcsr[i];

    int lane = t & 31, w = t >> 5;
    int c = lane & 3, grp = lane >> 2;
    float4 wr[8];
    const float4* w4 = (const float4*)(Wl + lane * HH);
#pragma unroll
    for (int q = 0; q < 8; q++) wr[q] = w4[q];
    float bv[8];
    {
        float4 ba = *(const float4*)(b2 + 8 * c);
        float4 bb = *(const float4*)(b2 + 8 * c + 4);
        bv[0]=ba.x; bv[1]=ba.y; bv[2]=ba.z; bv[3]=ba.w;
        bv[4]=bb.x; bv[5]=bb.y; bv[6]=bb.z; bv[7]=bb.w;
    }
    float blr = bl[lane];
    __syncthreads();

    const uint4* g4 = (const uint4*)sGh;
    float vsum = 0.0f;
    for (int nl = w * 16; nl < w * 16 + 16; nl++) {
        int start = sRp[nl], end = sRp[nl + 1];
        float dis = rsqrtf((float)(end - start) + 1.0f);
        int nodeRow = (h << 9) + nl;
        float acc[8];
        gatherNodeH(acc, g4, sCsr, start, end, nodeRow, grp, c);
        float uv[8];
#pragma unroll
        for (int j = 0; j < 8; j++) uv[j] = ftanh(fmaf(dis, acc[j], bv[j]));
        float a = blr;
#pragma unroll
        for (int k = 0; k < HH; k++) {
            float tk = __shfl_sync(0xffffffffu, uv[k & 7], k >> 3);
            a = fmaf(tk, ((const float*)wr)[k], a);
        }
        vsum += ftanh(a);
    }
    sRed[w * HH + lane] = vsum;
    __syncthreads();
    if (t < HH) {
        float s = 0.0f;
#pragma unroll
        for (int r = 0; r < 32; r++) s += sRed[r * HH + t];
        atomicAdd(&d_pool[g * HH + t], s);
    }
}

// ---------------- heads ----------------
__global__ void k_head(const float* __restrict__ share,
                       const float* __restrict__ Wp, const float* __restrict__ bp,
                       const float* __restrict__ Vw1, const float* __restrict__ Vb1,
                       const float* __restrict__ Vw2, const float* __restrict__ Vb2,
                       const float* __restrict__ Vw3, const float* __restrict__ Vb3,
                       const float* __restrict__ Cw1, const float* __restrict__ Cb1,
                       const float* __restrict__ Cw2, const float* __restrict__ Cb2,
                       float* __restrict__ out) {
    int b = threadIdx.x;
    if (b >= BB) return;
    float p[HH];
#pragma unroll
    for (int k = 0; k < HH; k++) p[k] = d_pool[b * HH + k];
    float h1[HH];
#pragma unroll
    for (int j = 0; j < HH; j++) {
        float a = bp[j];
#pragma unroll
        for (int k = 0; k < HH; k++) a = fmaf(p[k], Wp[j * HH + k], a);
        h1[j] = a;
    }
    float s[2 * HH];
#pragma unroll
    for (int k = 0; k < 2 * HH; k++) s[k] = share[b * 2 * HH + k];
    float a1[HH];
#pragma unroll
    for (int j = 0; j < HH; j++) {
        float a = Vb1[j];
#pragma unroll
        for (int k = 0; k < 2 * HH; k++) a = fmaf(s[k], Vw1[j * 2 * HH + k], a);
        a1[j] = tanhf(a);
    }
    float a2[HH];
#pragma unroll
    for (int j = 0; j < HH; j++) {
        float a = Vb2[j];
#pragma unroll
        for (int k = 0; k < HH; k++) a = fmaf(a1[k], Vw2[j * HH + k], a);
        a2[j] = tanhf(a);
    }
    float h2[HH];
#pragma unroll
    for (int j = 0; j < HH; j++) {
        float a = Vb3[j];
#pragma unroll
        for (int k = 0; k < HH; k++) a = fmaf(a2[k], Vw3[j * HH + k], a);
        h2[j] = a;
    }
    float val = Cb2[0];
#pragma unroll
    for (int j = 0; j < HH; j++) {
        float a = Cb1[j];
#pragma unroll
        for (int k = 0; k < HH; k++) a = fmaf(h1[k], Cw1[j * 2 * HH + k], a);
#pragma unroll
        for (int k = 0; k < HH; k++) a = fmaf(h2[k], Cw1[j * 2 * HH + HH + k], a);
        val = fmaf(tanhf(a), Cw2[j], val);
    }
    out[b] = val;
}

extern "C" void kernel_launch(void* const* d_in, const int* in_sizes, int n_in,
                              void* d_out, int out_size) {
    const float* x     = (const float*)d_in[0];
    const int*   ei    = (const int*)  d_in[1];
    const float* share = (const float*)d_in[3];
    const float* W1  = (const float*)d_in[4];
    const float* b1  = (const float*)d_in[5];
    const float* W2  = (const float*)d_in[6];
    const float* b2  = (const float*)d_in[7];
    const float* Wl  = (const float*)d_in[8];
    const float* bl  = (const float*)d_in[9];
    const float* Wp  = (const float*)d_in[10];
    const float* bp  = (const float*)d_in[11];
    const float* Vw1 = (const float*)d_in[12];
    const float* Vb1 = (const float*)d_in[13];
    const float* Vw2 = (const float*)d_in[14];
    const float* Vb2 = (const float*)d_in[15];
    const float* Vw3 = (const float*)d_in[16];
    const float* Vb3 = (const float*)d_in[17];
    const float* Cw1 = (const float*)d_in[18];
    const float* Cb1 = (const float*)d_in[19];
    const float* Cw2 = (const float*)d_in[20];
    const float* Cb2 = (const float*)d_in[21];

    int e = in_sizes[1] / 2;
    const int* src = ei;
    const int* dst = ei + e;

    int smA = GSTRIDE * 4 + 512 * 4 + 516 * 4 + HSTRIDE * 2 + HH * DIN * 4;  // ~190KB
    int smB = PP * HH * 2 + 516 * 4 + HSTRIDE * 2;                            // ~104.5KB
    int smC = smB + 32 * HH * 4;                                              // ~108.6KB

    cudaFuncSetAttribute(k_A, cudaFuncAttributeMaxDynamicSharedMemorySize, smA);
    cudaFuncSetAttribute(k_B, cudaFuncAttributeMaxDynamicSharedMemorySize, smB);
    cudaFuncSetAttribute(k_C, cudaFuncAttributeMaxDynamicSharedMemorySize, smC);

    k_z   <<<1, 1024>>>();
    k_bin <<<BCTA, 256>>>(src, dst);
    k_A   <<<128, 512, smA>>>(x, W1);
    k_B   <<<128, 1024, smB>>>(b1, W2);
    k_C   <<<128, 1024, smC>>>(b2, Wl, bl);
    k_head<<<1, 64>>>(share, Wp, bp, Vw1, Vb1, Vw2, Vb2, Vw3, Vb3,
                      Cw1, Cb1, Cw2, Cb2, (float*)d_out);
}

// round 11
// speedup vs baseline: 1.1027x; 1.1027x over previous
#include <cuda_runtime.h>

#define NN   65536
#define PP   1024
#define BB   64
#define HH   32
#define DIN  16
#define EE   2097152

#define BCTA   512
#define BEDGE  (EE / BCTA)
#define BINCAP 128
#define GSTRIDE 36864              // per-graph edge-bin capacity (ints)
#define HSTRIDE 18432              // per-half CSR capacity (ushorts)

// ---------------- device scratch ----------------
__device__ int            d_gcur[BB];
__device__ __align__(16) int d_binE[BB * GSTRIDE];     // packed (dst_local<<10|src_local)
__device__ __align__(16) unsigned short d_csrU[128 * HSTRIDE];
__device__ __align__(16) int d_rpH[128 * 513];
__device__ __align__(16) float d_G [NN * HH];
__device__ __align__(16) float d_G2[NN * HH];
__device__ __align__(16) float d_poolP[128 * HH];      // per-half partial pools

__device__ __forceinline__ float ftanh(float x) {
    float e = __expf(2.0f * x);
    return 1.0f - __fdividef(2.0f, e + 1.0f);
}

// ---------------- zero cursors ----------------
__global__ void k_z() {
    int t = threadIdx.x;
    if (t < BB) d_gcur[t] = 0;
}

// ---------------- one-pass binning ----------------
__global__ void k_bin(const int* __restrict__ src, const int* __restrict__ dst) {
    __shared__ int bins[BB][BINCAP];
    __shared__ int cur[BB];
    __shared__ int gbase[BB];
    int t = threadIdx.x;
    if (t < BB) cur[t] = 0;
    __syncthreads();
    int base = blockIdx.x * BEDGE;
    for (int i = t; i < BEDGE; i += 256) {
        int s = src[base + i], d = dst[base + i];
        int g = d >> 10;
        int pk = ((d & 1023) << 10) | (s & 1023);
        int p = atomicAdd(&cur[g], 1);
        if (p < BINCAP) bins[g][p] = pk;
        else {
            int q = atomicAdd(&d_gcur[g], 1);
            d_binE[g * GSTRIDE + q] = pk;
        }
    }
    __syncthreads();
    if (t < BB) {
        int m = cur[t]; if (m > BINCAP) m = BINCAP;
        gbase[t] = atomicAdd(&d_gcur[t], m);
    }
    __syncthreads();
    int w = t >> 5, lane = t & 31;
    for (int g = w; g < BB; g += 8) {
        int m = cur[g]; if (m > BINCAP) m = BINCAP;
        int gb = g * GSTRIDE + gbase[g];
        for (int i = lane; i < m; i += 32)
            d_binE[gb + i] = bins[g][i];
    }
}

// ---------------- A: per-half local CSR build + message compute ----------------
// grid 128 (2 per graph), block 1024; edge bin read directly from L2 (twice)
__global__ void __launch_bounds__(1024) k_A(const float* __restrict__ x,
                                            const float* __restrict__ W1) {
    extern __shared__ int smA[];
    int* sCnt  = smA;                                  // 512
    int* sRow  = sCnt + 512;                           // 513 (+3)
    unsigned short* sCsrU = (unsigned short*)(sRow + 516);   // HSTRIDE ushorts
    float* sW  = (float*)(sCsrU + HSTRIDE);            // 16x32 transposed W1

    int t = threadIdx.x;
    int g = blockIdx.x >> 1, h = blockIdx.x & 1;
    int tot = d_gcur[g];
    const int* bin = d_binE + g * GSTRIDE;

    if (t < 512) sCnt[t] = 0;
    if (t < HH * DIN) sW[(t & 15) * HH + (t >> 4)] = W1[t];
    __syncthreads();

    for (int i = t; i < tot; i += 1024) {
        int e = bin[i]; int dl = e >> 10;
        if ((dl >> 9) == h) atomicAdd(&sCnt[dl & 511], 1);
    }
    __syncthreads();
    if (t < 32) {
        int loc[16]; int s = 0;
#pragma unroll
        for (int i = 0; i < 16; i++) { loc[i] = sCnt[t * 16 + i]; s += loc[i]; }
        int run = s;
#pragma unroll
        for (int off = 1; off < 32; off <<= 1) {
            int v = __shfl_up_sync(0xffffffffu, run, off);
            if (t >= off) run += v;
        }
        int excl = run - s;
#pragma unroll
        for (int i = 0; i < 16; i++) { sRow[t * 16 + i] = excl; excl += loc[i]; }
        if (t == 31) sRow[512] = excl;
    }
    __syncthreads();
    if (t < 512) sCnt[t] = sRow[t];
    __syncthreads();
    for (int i = t; i < tot; i += 1024) {
        int e = bin[i]; int dl = e >> 10;
        if ((dl >> 9) == h) {
            int p = atomicAdd(&sCnt[dl & 511], 1);
            sCsrU[p] = (unsigned short)(e & 1023);
        }
    }
    __syncthreads();

    int half = blockIdx.x;
    int m = sRow[512];
    unsigned int* gcsr = (unsigned int*)(d_csrU + (size_t)half * HSTRIDE);
    const unsigned int* scsr = (const unsigned int*)sCsrU;
    for (int i = t; i < (m + 1) / 2; i += 1024) gcsr[i] = scsr[i];
    if (t < 513) d_rpH[half * 513 + t] = sRow[t];

    // messages: thread-pair per node; qh selects 4 of 8 float4 outputs
    {
        int nl = t >> 1, qh = t & 1;
        int node = g * PP + (h << 9) + nl;
        float xv[DIN];
        const float4* xp = (const float4*)(x + (size_t)node * DIN);
#pragma unroll
        for (int i = 0; i < DIN / 4; i++) {
            float4 v = xp[i];
            xv[4*i] = v.x; xv[4*i+1] = v.y; xv[4*i+2] = v.z; xv[4*i+3] = v.w;
        }
        float dis = rsqrtf((float)(sRow[nl + 1] - sRow[nl]) + 1.0f);
        float4 a[4];
#pragma unroll
        for (int q = 0; q < 4; q++) a[q] = make_float4(0.f, 0.f, 0.f, 0.f);
        const float4* sW4 = (const float4*)sW;
#pragma unroll
        for (int ii = 0; ii < DIN; ii++) {
            float xi = xv[ii];
#pragma unroll
            for (int q = 0; q < 4; q++) {
                float4 w = sW4[ii * 8 + qh * 4 + q];
                a[q].x = fmaf(xi, w.x, a[q].x);
                a[q].y = fmaf(xi, w.y, a[q].y);
                a[q].z = fmaf(xi, w.z, a[q].z);
                a[q].w = fmaf(xi, w.w, a[q].w);
            }
        }
        float4* gp = (float4*)(d_G + (size_t)node * HH) + qh * 4;
#pragma unroll
        for (int q = 0; q < 4; q++) {
            a[q].x *= dis; a[q].y *= dis; a[q].z *= dis; a[q].w *= dis;
            gp[q] = a[q];
        }
    }
}

// accumulate helper
#define ACC4(A, V) { A.x += V.x; A.y += V.y; A.z += V.z; A.w += V.w; }

// ---------------- B: layer-1 gather (2-node interleaved) + W2 transform ----------------
__global__ void __launch_bounds__(1024) k_B(const float* __restrict__ b1,
                                            const float* __restrict__ W2) {
    extern __shared__ char smB[];
    float* sG = (float*)smB;                           // 128KB
    int*   sRp = (int*)(smB + PP * HH * 4);            // 513 (+3)
    unsigned short* sCsr = (unsigned short*)(sRp + 516);
    float* sB = (float*)(sCsr + HSTRIDE);              // 32 bias
    int t = threadIdx.x;
    int g = blockIdx.x >> 1, h = blockIdx.x & 1, half = blockIdx.x;

    const float4* gs = (const float4*)(d_G + (size_t)g * PP * HH);
    float4* sg4 = (float4*)sG;
    for (int i = t; i < PP * HH / 4; i += 1024) sg4[i] = gs[i];
    if (t < 513) sRp[t] = d_rpH[half * 513 + t];
    if (t >= 992) sB[t - 992] = b1[t - 992];
    __syncthreads();
    int m = sRp[512];
    const unsigned int* gcsr = (const unsigned int*)(d_csrU + (size_t)half * HSTRIDE);
    unsigned int* scsr = (unsigned int*)sCsr;
    for (int i = t; i < (m + 1) / 2; i += 1024) scsr[i] = gcsr[i];

    int lane = t & 31, w = t >> 5;
    int c = lane & 7, g3 = lane >> 3;
    float4 wr[8];
    const float4* w4 = (const float4*)(W2 + lane * HH);
#pragma unroll
    for (int q = 0; q < 8; q++) wr[q] = w4[q];
    __syncthreads();

    const float4* g4 = (const float4*)sG;
    float* outBase = d_G2 + (size_t)g * PP * HH + ((size_t)(h << 9) << 5);
    for (int nn = 0; nn < 16; nn += 2) {
        int nl0 = w * 16 + nn, nl1 = nl0 + 1;
        int s0 = sRp[nl0], e0 = sRp[nl0 + 1];
        int s1 = e0,        e1 = sRp[nl1 + 1];   // rows contiguous: sRp[nl1]==e0
        float4 a0 = make_float4(0.f,0.f,0.f,0.f);
        float4 a1 = make_float4(0.f,0.f,0.f,0.f);
        int p0 = s0, p1 = s1;
        // joint main loop: two independent LDS chains
        for (; p0 + 32 <= e0 && p1 + 32 <= e1; p0 += 32, p1 += 32) {
#pragma unroll
            for (int i = 0; i < 4; i++) {
                int i0a = (int)sCsr[p0 + (2*i)   * 4 + g3];
                int i0b = (int)sCsr[p0 + (2*i+1) * 4 + g3];
                int i1a = (int)sCsr[p1 + (2*i)   * 4 + g3];
                int i1b = (int)sCsr[p1 + (2*i+1) * 4 + g3];
                float4 v0a = g4[i0a * 8 + c]; ACC4(a0, v0a);
                float4 v1a = g4[i1a * 8 + c]; ACC4(a1, v1a);
                float4 v0b = g4[i0b * 8 + c]; ACC4(a0, v0b);
                float4 v1b = g4[i1b * 8 + c]; ACC4(a1, v1b);
            }
        }
        for (; p0 + 32 <= e0; p0 += 32) {
#pragma unroll
            for (int i = 0; i < 8; i++) {
                int s = (int)sCsr[p0 + i * 4 + g3];
                float4 v = g4[s * 8 + c]; ACC4(a0, v);
            }
        }
        for (int j = p0 + g3; j < e0; j += 4) {
            int s = (int)sCsr[j];
            float4 v = g4[s * 8 + c]; ACC4(a0, v);
        }
        for (; p1 + 32 <= e1; p1 += 32) {
#pragma unroll
            for (int i = 0; i < 8; i++) {
                int s = (int)sCsr[p1 + i * 4 + g3];
                float4 v = g4[s * 8 + c]; ACC4(a1, v);
            }
        }
        for (int j = p1 + g3; j < e1; j += 4) {
            int s = (int)sCsr[j];
            float4 v = g4[s * 8 + c]; ACC4(a1, v);
        }
#pragma unroll
        for (int d = 8; d <= 16; d <<= 1) {
            a0.x += __shfl_xor_sync(0xffffffffu, a0.x, d);
            a0.y += __shfl_xor_sync(0xffffffffu, a0.y, d);
            a0.z += __shfl_xor_sync(0xffffffffu, a0.z, d);
            a0.w += __shfl_xor_sync(0xffffffffu, a0.w, d);
            a1.x += __shfl_xor_sync(0xffffffffu, a1.x, d);
            a1.y += __shfl_xor_sync(0xffffffffu, a1.y, d);
            a1.z += __shfl_xor_sync(0xffffffffu, a1.z, d);
            a1.w += __shfl_xor_sync(0xffffffffu, a1.w, d);
        }
        {
            float4 sv0 = g4[((h << 9) + nl0) * 8 + c]; ACC4(a0, sv0);
            float4 sv1 = g4[((h << 9) + nl1) * 8 + c]; ACC4(a1, sv1);
        }
        float dis0 = rsqrtf((float)(e0 - s0) + 1.0f);
        float dis1 = rsqrtf((float)(e1 - s1) + 1.0f);
        float4 bb = ((const float4*)sB)[c];
        a0.x = ftanh(fmaf(dis0, a0.x, bb.x));
        a0.y = ftanh(fmaf(dis0, a0.y, bb.y));
        a0.z = ftanh(fmaf(dis0, a0.z, bb.z));
        a0.w = ftanh(fmaf(dis0, a0.w, bb.w));
        a1.x = ftanh(fmaf(dis1, a1.x, bb.x));
        a1.y = ftanh(fmaf(dis1, a1.y, bb.y));
        a1.z = ftanh(fmaf(dis1, a1.z, bb.z));
        a1.w = ftanh(fmaf(dis1, a1.w, bb.w));
        float o0 = 0.0f, o1 = 0.0f;
        const float* wf = (const float*)wr;
#pragma unroll
        for (int kc = 0; kc < 8; kc++) {
            float u0 = __shfl_sync(0xffffffffu, a0.x, kc);
            float u1 = __shfl_sync(0xffffffffu, a1.x, kc);
            o0 = fmaf(u0, wf[4*kc+0], o0); o1 = fmaf(u1, wf[4*kc+0], o1);
            u0 = __shfl_sync(0xffffffffu, a0.y, kc);
            u1 = __shfl_sync(0xffffffffu, a1.y, kc);
            o0 = fmaf(u0, wf[4*kc+1], o0); o1 = fmaf(u1, wf[4*kc+1], o1);
            u0 = __shfl_sync(0xffffffffu, a0.z, kc);
            u1 = __shfl_sync(0xffffffffu, a1.z, kc);
            o0 = fmaf(u0, wf[4*kc+2], o0); o1 = fmaf(u1, wf[4*kc+2], o1);
            u0 = __shfl_sync(0xffffffffu, a0.w, kc);
            u1 = __shfl_sync(0xffffffffu, a1.w, kc);
            o0 = fmaf(u0, wf[4*kc+3], o0); o1 = fmaf(u1, wf[4*kc+3], o1);
        }
        outBase[(size_t)nl0 * HH + lane] = o0 * dis0;
        outBase[(size_t)nl1 * HH + lane] = o1 * dis1;
    }
}

// ---------------- C: layer-2 gather (2-node interleaved) + Wl + pool partials ----------------
__global__ void __launch_bounds__(1024) k_C(const float* __restrict__ b2,
                                            const float* __restrict__ Wl,
                                            const float* __restrict__ bl) {
    extern __shared__ char smC[];
    float* sG = (float*)smC;
    int*   sRp = (int*)(smC + PP * HH * 4);
    unsigned short* sCsr = (unsigned short*)(sRp + 516);
    float* sB = (float*)(sCsr + HSTRIDE);              // 32 bias (b2)
    float* sRed = sB + 32;                             // 32x32
    int t = threadIdx.x;
    int g = blockIdx.x >> 1, h = blockIdx.x & 1, half = blockIdx.x;

    const float4* gs = (const float4*)(d_G2 + (size_t)g * PP * HH);
    float4* sg4 = (float4*)sG;
    for (int i = t; i < PP * HH / 4; i += 1024) sg4[i] = gs[i];
    if (t < 513) sRp[t] = d_rpH[half * 513 + t];
    if (t >= 992) sB[t - 992] = b2[t - 992];
    __syncthreads();
    int m = sRp[512];
    const unsigned int* gcsr = (const unsigned int*)(d_csrU + (size_t)half * HSTRIDE);
    unsigned int* scsr = (unsigned int*)sCsr;
    for (int i = t; i < (m + 1) / 2; i += 1024) scsr[i] = gcsr[i];

    int lane = t & 31, w = t >> 5;
    int c = lane & 7, g3 = lane >> 3;
    float4 wr[8];
    const float4* w4 = (const float4*)(Wl + lane * HH);
#pragma unroll
    for (int q = 0; q < 8; q++) wr[q] = w4[q];
    float blr = bl[lane];
    __syncthreads();

    const float4* g4 = (const float4*)sG;
    float vsum = 0.0f;
    for (int nn = 0; nn < 16; nn += 2) {
        int nl0 = w * 16 + nn, nl1 = nl0 + 1;
        int s0 = sRp[nl0], e0 = sRp[nl0 + 1];
        int s1 = e0,        e1 = sRp[nl1 + 1];
        float4 a0 = make_float4(0.f,0.f,0.f,0.f);
        float4 a1 = make_float4(0.f,0.f,0.f,0.f);
        int p0 = s0, p1 = s1;
        for (; p0 + 32 <= e0 && p1 + 32 <= e1; p0 += 32, p1 += 32) {
#pragma unroll
            for (int i = 0; i < 4; i++) {
                int i0a = (int)sCsr[p0 + (2*i)   * 4 + g3];
                int i0b = (int)sCsr[p0 + (2*i+1) * 4 + g3];
                int i1a = (int)sCsr[p1 + (2*i)   * 4 + g3];
                int i1b = (int)sCsr[p1 + (2*i+1) * 4 + g3];
                float4 v0a = g4[i0a * 8 + c]; ACC4(a0, v0a);
                float4 v1a = g4[i1a * 8 + c]; ACC4(a1, v1a);
                float4 v0b = g4[i0b * 8 + c]; ACC4(a0, v0b);
                float4 v1b = g4[i1b * 8 + c]; ACC4(a1, v1b);
            }
        }
        for (; p0 + 32 <= e0; p0 += 32) {
#pragma unroll
            for (int i = 0; i < 8; i++) {
                int s = (int)sCsr[p0 + i * 4 + g3];
                float4 v = g4[s * 8 + c]; ACC4(a0, v);
            }
        }
        for (int j = p0 + g3; j < e0; j += 4) {
            int s = (int)sCsr[j];
            float4 v = g4[s * 8 + c]; ACC4(a0, v);
        }
        for (; p1 + 32 <= e1; p1 += 32) {
#pragma unroll
            for (int i = 0; i < 8; i++) {
                int s = (int)sCsr[p1 + i * 4 + g3];
                float4 v = g4[s * 8 + c]; ACC4(a1, v);
            }
        }
        for (int j = p1 + g3; j < e1; j += 4) {
            int s = (int)sCsr[j];
            float4 v = g4[s * 8 + c]; ACC4(a1, v);
        }
#pragma unroll
        for (int d = 8; d <= 16; d <<= 1) {
            a0.x += __shfl_xor_sync(0xffffffffu, a0.x, d);
            a0.y += __shfl_xor_sync(0xffffffffu, a0.y, d);
            a0.z += __shfl_xor_sync(0xffffffffu, a0.z, d);
            a0.w += __shfl_xor_sync(0xffffffffu, a0.w, d);
            a1.x += __shfl_xor_sync(0xffffffffu, a1.x, d);
            a1.y += __shfl_xor_sync(0xffffffffu, a1.y, d);
            a1.z += __shfl_xor_sync(0xffffffffu, a1.z, d);
            a1.w += __shfl_xor_sync(0xffffffffu, a1.w, d);
        }
        {
            float4 sv0 = g4[((h << 9) + nl0) * 8 + c]; ACC4(a0, sv0);
            float4 sv1 = g4[((h << 9) + nl1) * 8 + c]; ACC4(a1, sv1);
        }
        float dis0 = rsqrtf((float)(e0 - s0) + 1.0f);
        float dis1 = rsqrtf((float)(e1 - s1) + 1.0f);
        float4 bb = ((const float4*)sB)[c];
        a0.x = ftanh(fmaf(dis0, a0.x, bb.x));
        a0.y = ftanh(fmaf(dis0, a0.y, bb.y));
        a0.z = ftanh(fmaf(dis0, a0.z, bb.z));
        a0.w = ftanh(fmaf(dis0, a0.w, bb.w));
        a1.x = ftanh(fmaf(dis1, a1.x, bb.x));
        a1.y = ftanh(fmaf(dis1, a1.y, bb.y));
        a1.z = ftanh(fmaf(dis1, a1.z, bb.z));
        a1.w = ftanh(fmaf(dis1, a1.w, bb.w));
        float o0 = blr, o1 = blr;
        const float* wf = (const float*)wr;
#pragma unroll
        for (int kc = 0; kc < 8; kc++) {
            float u0 = __shfl_sync(0xffffffffu, a0.x, kc);
            float u1 = __shfl_sync(0xffffffffu, a1.x, kc);
            o0 = fmaf(u0, wf[4*kc+0], o0); o1 = fmaf(u1, wf[4*kc+0], o1);
            u0 = __shfl_sync(0xffffffffu, a0.y, kc);
            u1 = __shfl_sync(0xffffffffu, a1.y, kc);
            o0 = fmaf(u0, wf[4*kc+1], o0); o1 = fmaf(u1, wf[4*kc+1], o1);
            u0 = __shfl_sync(0xffffffffu, a0.z, kc);
            u1 = __shfl_sync(0xffffffffu, a1.z, kc);
            o0 = fmaf(u0, wf[4*kc+2], o0); o1 = fmaf(u1, wf[4*kc+2], o1);
            u0 = __shfl_sync(0xffffffffu, a0.w, kc);
            u1 = __shfl_sync(0xffffffffu, a1.w, kc);
            o0 = fmaf(u0, wf[4*kc+3], o0); o1 = fmaf(u1, wf[4*kc+3], o1);
        }
        vsum += ftanh(o0) + ftanh(o1);
    }
    sRed[w * HH + lane] = vsum;
    __syncthreads();
    if (t < HH) {
        float s = 0.0f;
#pragma unroll
        for (int r = 0; r < 32; r++) s += sRed[r * HH + t];
        d_poolP[half * HH + t] = s;          // partial: no atomics, no pre-zero
    }
}

// ---------------- heads ----------------
__global__ void k_head(const float* __restrict__ share,
                       const float* __restrict__ Wp, const float* __restrict__ bp,
                       const float* __restrict__ Vw1, const float* __restrict__ Vb1,
                       const float* __restrict__ Vw2, const float* __restrict__ Vb2,
                       const float* __restrict__ Vw3, const float* __restrict__ Vb3,
                       const float* __restrict__ Cw1, const float* __restrict__ Cb1,
                       const float* __restrict__ Cw2, const float* __restrict__ Cb2,
                       float* __restrict__ out) {
    int b = threadIdx.x;
    if (b >= BB) return;
    float p[HH];
#pragma unroll
    for (int k = 0; k < HH; k++)
        p[k] = d_poolP[(2*b) * HH + k] + d_poolP[(2*b+1) * HH + k];
    float h1[HH];
#pragma unroll
    for (int j = 0; j < HH; j++) {
        float a = bp[j];
#pragma unroll
        for (int k = 0; k < HH; k++) a = fmaf(p[k], Wp[j * HH + k], a);
        h1[j] = a;
    }
    float s[2 * HH];
#pragma unroll
    for (int k = 0; k < 2 * HH; k++) s[k] = share[b * 2 * HH + k];
    float a1[HH];
#pragma unroll
    for (int j = 0; j < HH; j++) {
        float a = Vb1[j];
#pragma unroll
        for (int k = 0; k < 2 * HH; k++) a = fmaf(s[k], Vw1[j * 2 * HH + k], a);
        a1[j] = tanhf(a);
    }
    float a2[HH];
#pragma unroll
    for (int j = 0; j < HH; j++) {
        float a = Vb2[j];
#pragma unroll
        for (int k = 0; k < HH; k++) a = fmaf(a1[k], Vw2[j * HH + k], a);
        a2[j] = tanhf(a);
    }
    float h2[HH];
#pragma unroll
    for (int j = 0; j < HH; j++) {
        float a = Vb3[j];
#pragma unroll
        for (int k = 0; k < HH; k++) a = fmaf(a2[k], Vw3[j * HH + k], a);
        h2[j] = a;
    }
    float val = Cb2[0];
#pragma unroll
    for (int j = 0; j < HH; j++) {
        float a = Cb1[j];
#pragma unroll
        for (int k = 0; k < HH; k++) a = fmaf(h1[k], Cw1[j * 2 * HH + k], a);
#pragma unroll
        for (int k = 0; k < HH; k++) a = fmaf(h2[k], Cw1[j * 2 * HH + HH + k], a);
        val = fmaf(tanhf(a), Cw2[j], val);
    }
    out[b] = val;
}

extern "C" void kernel_launch(void* const* d_in, const int* in_sizes, int n_in,
                              void* d_out, int out_size) {
    const float* x     = (const float*)d_in[0];
    const int*   ei    = (const int*)  d_in[1];
    const float* share = (const float*)d_in[3];
    const float* W1  = (const float*)d_in[4];
    const float* b1  = (const float*)d_in[5];
    const float* W2  = (const float*)d_in[6];
    const float* b2  = (const float*)d_in[7];
    const float* Wl  = (const float*)d_in[8];
    const float* bl  = (const float*)d_in[9];
    const float* Wp  = (const float*)d_in[10];
    const float* bp  = (const float*)d_in[11];
    const float* Vw1 = (const float*)d_in[12];
    const float* Vb1 = (const float*)d_in[13];
    const float* Vw2 = (const float*)d_in[14];
    const float* Vb2 = (const float*)d_in[15];
    const float* Vw3 = (const float*)d_in[16];
    const float* Vb3 = (const float*)d_in[17];
    const float* Cw1 = (const float*)d_in[18];
    const float* Cb1 = (const float*)d_in[19];
    const float* Cw2 = (const float*)d_in[20];
    const float* Cb2 = (const float*)d_in[21];

    int e = in_sizes[1] / 2;
    const int* src = ei;
    const int* dst = ei + e;

    int smA = 512 * 4 + 516 * 4 + HSTRIDE * 2 + HH * DIN * 4;      // ~43KB
    int smB = PP * HH * 4 + 516 * 4 + HSTRIDE * 2 + 32 * 4;        // ~170KB
    int smC = smB + 32 * HH * 4;                                   // ~174KB

    cudaFuncSetAttribute(k_A, cudaFuncAttributeMaxDynamicSharedMemorySize, smA);
    cudaFuncSetAttribute(k_B, cudaFuncAttributeMaxDynamicSharedMemorySize, smB);
    cudaFuncSetAttribute(k_C, cudaFuncAttributeMaxDynamicSharedMemorySize, smC);

    k_z   <<<1, 64>>>();
    k_bin <<<BCTA, 256>>>(src, dst);
    k_A   <<<128, 1024, smA>>>(x, W1);
    k_B   <<<128, 1024, smB>>>(b1, W2);
    k_C   <<<128, 1024, smC>>>(b2, Wl, bl);
    k_head<<<1, 64>>>(share, Wp, bp, Vw1, Vb1, Vw2, Vb2, Vw3, Vb3,
                      Cw1, Cb1, Cw2, Cb2, (float*)d_out);
}

// round 12
// speedup vs baseline: 1.1149x; 1.0111x over previous
#include <cuda_runtime.h>

#define NN   65536
#define PP   1024
#define BB   64
#define HH   32
#define DIN  16
#define EE   2097152

#define BCTA   512
#define BEDGE  (EE / BCTA)
#define BINCAP 128
#define GSTRIDE 36864              // per-graph edge-bin capacity (ints)
#define HSTRIDE 18432              // per-half CSR capacity (ushorts)

// ---------------- device scratch ----------------
__device__ int            d_gcur[BB];
__device__ __align__(16) int d_binE[BB * GSTRIDE];
__device__ __align__(16) unsigned short d_csrU[128 * HSTRIDE];
__device__ __align__(16) int d_rpH[128 * 513];
__device__ __align__(16) float d_G [NN * HH];
__device__ __align__(16) float d_G2[NN * HH];
__device__ __align__(16) float d_poolP[128 * HH];

__device__ __forceinline__ float tanha(float x) {        // MUFU.TANH
    float y; asm("tanh.approx.f32 %0, %1;" : "=f"(y) : "f"(x)); return y;
}
__device__ __forceinline__ float ftanh(float x) {        // precise-ish (head path)
    float e = __expf(2.0f * x);
    return 1.0f - __fdividef(2.0f, e + 1.0f);
}
// packed f32x2 load-and-accumulate: one LDS.128 -> two add.rn.f32x2
__device__ __forceinline__ void ldsAdd(unsigned long long& lo, unsigned long long& hi,
                                       unsigned int addr) {
    unsigned long long vlo, vhi;
    asm volatile("ld.shared.v2.u64 {%0,%1}, [%2];" : "=l"(vlo), "=l"(vhi) : "r"(addr));
    asm("add.rn.f32x2 %0, %0, %1;" : "+l"(lo) : "l"(vlo));
    asm("add.rn.f32x2 %0, %0, %1;" : "+l"(hi) : "l"(vhi));
}
#define UNPACK2(p, x, y) asm("mov.b64 {%0,%1}, %2;" : "=f"(x), "=f"(y) : "l"(p))

// ---------------- zero cursors ----------------
__global__ void k_z() {
    int t = threadIdx.x;
    if (t < BB) d_gcur[t] = 0;
}

// ---------------- one-pass binning ----------------
__global__ void k_bin(const int* __restrict__ src, const int* __restrict__ dst) {
    __shared__ int bins[BB][BINCAP];
    __shared__ int cur[BB];
    __shared__ int gbase[BB];
    int t = threadIdx.x;
    if (t < BB) cur[t] = 0;
    __syncthreads();
    int base = blockIdx.x * BEDGE;
    for (int i = t; i < BEDGE; i += 256) {
        int s = src[base + i], d = dst[base + i];
        int g = d >> 10;
        int pk = ((d & 1023) << 10) | (s & 1023);
        int p = atomicAdd(&cur[g], 1);
        if (p < BINCAP) bins[g][p] = pk;
        else {
            int q = atomicAdd(&d_gcur[g], 1);
            d_binE[g * GSTRIDE + q] = pk;
        }
    }
    __syncthreads();
    if (t < BB) {
        int m = cur[t]; if (m > BINCAP) m = BINCAP;
        gbase[t] = atomicAdd(&d_gcur[t], m);
    }
    __syncthreads();
    int w = t >> 5, lane = t & 31;
    for (int g = w; g < BB; g += 8) {
        int m = cur[g]; if (m > BINCAP) m = BINCAP;
        int gb = g * GSTRIDE + gbase[g];
        for (int i = lane; i < m; i += 32)
            d_binE[gb + i] = bins[g][i];
    }
}

// ---------------- A: per-half local CSR build + message compute ----------------
__global__ void __launch_bounds__(1024) k_A(const float* __restrict__ x,
                                            const float* __restrict__ W1) {
    extern __shared__ int smA[];
    int* sCnt  = smA;                                  // 512
    int* sRow  = sCnt + 512;                           // 513 (+3)
    unsigned short* sCsrU = (unsigned short*)(sRow + 516);
    float* sW  = (float*)(sCsrU + HSTRIDE);

    int t = threadIdx.x;
    int g = blockIdx.x >> 1, h = blockIdx.x & 1;
    int tot = d_gcur[g];
    const int* bin = d_binE + g * GSTRIDE;

    if (t < 512) sCnt[t] = 0;
    if (t < HH * DIN) sW[(t & 15) * HH + (t >> 4)] = W1[t];
    __syncthreads();

    for (int i = t; i < tot; i += 1024) {
        int e = bin[i]; int dl = e >> 10;
        if ((dl >> 9) == h) atomicAdd(&sCnt[dl & 511], 1);
    }
    __syncthreads();
    if (t < 32) {
        int loc[16]; int s = 0;
#pragma unroll
        for (int i = 0; i < 16; i++) { loc[i] = sCnt[t * 16 + i]; s += loc[i]; }
        int run = s;
#pragma unroll
        for (int off = 1; off < 32; off <<= 1) {
            int v = __shfl_up_sync(0xffffffffu, run, off);
            if (t >= off) run += v;
        }
        int excl = run - s;
#pragma unroll
        for (int i = 0; i < 16; i++) { sRow[t * 16 + i] = excl; excl += loc[i]; }
        if (t == 31) sRow[512] = excl;
    }
    __syncthreads();
    if (t < 512) sCnt[t] = sRow[t];
    __syncthreads();
    for (int i = t; i < tot; i += 1024) {
        int e = bin[i]; int dl = e >> 10;
        if ((dl >> 9) == h) {
            int p = atomicAdd(&sCnt[dl & 511], 1);
            sCsrU[p] = (unsigned short)(e & 1023);
        }
    }
    __syncthreads();

    int half = blockIdx.x;
    int m = sRow[512];
    unsigned int* gcsr = (unsigned int*)(d_csrU + (size_t)half * HSTRIDE);
    const unsigned int* scsr = (const unsigned int*)sCsrU;
    for (int i = t; i < (m + 1) / 2; i += 1024) gcsr[i] = scsr[i];
    if (t < 513) d_rpH[half * 513 + t] = sRow[t];

    {
        int nl = t >> 1, qh = t & 1;
        int node = g * PP + (h << 9) + nl;
        float xv[DIN];
        const float4* xp = (const float4*)(x + (size_t)node * DIN);
#pragma unroll
        for (int i = 0; i < DIN / 4; i++) {
            float4 v = xp[i];
            xv[4*i] = v.x; xv[4*i+1] = v.y; xv[4*i+2] = v.z; xv[4*i+3] = v.w;
        }
        float dis = rsqrtf((float)(sRow[nl + 1] - sRow[nl]) + 1.0f);
        float4 a[4];
#pragma unroll
        for (int q = 0; q < 4; q++) a[q] = make_float4(0.f, 0.f, 0.f, 0.f);
        const float4* sW4 = (const float4*)sW;
#pragma unroll
        for (int ii = 0; ii < DIN; ii++) {
            float xi = xv[ii];
#pragma unroll
            for (int q = 0; q < 4; q++) {
                float4 w = sW4[ii * 8 + qh * 4 + q];
                a[q].x = fmaf(xi, w.x, a[q].x);
                a[q].y = fmaf(xi, w.y, a[q].y);
                a[q].z = fmaf(xi, w.z, a[q].z);
                a[q].w = fmaf(xi, w.w, a[q].w);
            }
        }
        float4* gp = (float4*)(d_G + (size_t)node * HH) + qh * 4;
#pragma unroll
        for (int q = 0; q < 4; q++) {
            a[q].x *= dis; a[q].y *= dis; a[q].z *= dis; a[q].w *= dis;
            gp[q] = a[q];
        }
    }
}

#define ACC4(A, V) { A.x += V.x; A.y += V.y; A.z += V.z; A.w += V.w; }

// ---------------- B: layer-1 gather (packed f32x2) + W2 transform ----------------
__global__ void __launch_bounds__(1024) k_B(const float* __restrict__ b1,
                                            const float* __restrict__ W2) {
    extern __shared__ char smB[];
    float* sG = (float*)smB;                           // 128KB
    int*   sRp = (int*)(smB + PP * HH * 4);            // 513 (+3)
    unsigned short* sCsr = (unsigned short*)(sRp + 516);
    float* sB = (float*)(sCsr + HSTRIDE);              // 32 bias
    int t = threadIdx.x;
    int g = blockIdx.x >> 1, h = blockIdx.x & 1, half = blockIdx.x;

    const float4* gs = (const float4*)(d_G + (size_t)g * PP * HH);
    float4* sg4 = (float4*)sG;
    for (int i = t; i < PP * HH / 4; i += 1024) sg4[i] = gs[i];
    if (t < 513) sRp[t] = d_rpH[half * 513 + t];
    if (t >= 992) sB[t - 992] = b1[t - 992];
    __syncthreads();
    int m = sRp[512];
    const unsigned int* gcsr = (const unsigned int*)(d_csrU + (size_t)half * HSTRIDE);
    unsigned int* scsr = (unsigned int*)sCsr;
    for (int i = t; i < (m + 1) / 2; i += 1024) scsr[i] = gcsr[i];

    int lane = t & 31, w = t >> 5;
    int c = lane & 7, g3 = lane >> 3;
    float4 wr[8];
    const float4* w4 = (const float4*)(W2 + lane * HH);
#pragma unroll
    for (int q = 0; q < 8; q++) wr[q] = w4[q];
    unsigned int sGa = (unsigned int)__cvta_generic_to_shared(sG) + (c << 4);
    __syncthreads();

    const float4* g4 = (const float4*)sG;
    float* outBase = d_G2 + (size_t)g * PP * HH + ((size_t)(h << 9) << 5);
    for (int nn = 0; nn < 16; nn += 2) {
        int nl0 = w * 16 + nn, nl1 = nl0 + 1;
        int s0 = sRp[nl0], e0 = sRp[nl0 + 1];
        int s1 = e0,        e1 = sRp[nl1 + 1];
        unsigned long long a0l = 0, a0h = 0, a1l = 0, a1h = 0;
        int p0 = s0, p1 = s1;
        for (; p0 + 32 <= e0 && p1 + 32 <= e1; p0 += 32, p1 += 32) {
#pragma unroll
            for (int i = 0; i < 4; i++) {
                int i0a = (int)sCsr[p0 + (2*i)   * 4 + g3];
                int i0b = (int)sCsr[p0 + (2*i+1) * 4 + g3];
                int i1a = (int)sCsr[p1 + (2*i)   * 4 + g3];
                int i1b = (int)sCsr[p1 + (2*i+1) * 4 + g3];
                ldsAdd(a0l, a0h, sGa + (i0a << 7));
                ldsAdd(a1l, a1h, sGa + (i1a << 7));
                ldsAdd(a0l, a0h, sGa + (i0b << 7));
                ldsAdd(a1l, a1h, sGa + (i1b << 7));
            }
        }
        for (; p0 + 32 <= e0; p0 += 32) {
#pragma unroll
            for (int i = 0; i < 8; i++) {
                int s = (int)sCsr[p0 + i * 4 + g3];
                ldsAdd(a0l, a0h, sGa + (s << 7));
            }
        }
        for (int j = p0 + g3; j < e0; j += 4) {
            int s = (int)sCsr[j];
            ldsAdd(a0l, a0h, sGa + (s << 7));
        }
        for (; p1 + 32 <= e1; p1 += 32) {
#pragma unroll
            for (int i = 0; i < 8; i++) {
                int s = (int)sCsr[p1 + i * 4 + g3];
                ldsAdd(a1l, a1h, sGa + (s << 7));
            }
        }
        for (int j = p1 + g3; j < e1; j += 4) {
            int s = (int)sCsr[j];
            ldsAdd(a1l, a1h, sGa + (s << 7));
        }
        float4 a0, a1;
        UNPACK2(a0l, a0.x, a0.y); UNPACK2(a0h, a0.z, a0.w);
        UNPACK2(a1l, a1.x, a1.y); UNPACK2(a1h, a1.z, a1.w);
#pragma unroll
        for (int d = 8; d <= 16; d <<= 1) {
            a0.x += __shfl_xor_sync(0xffffffffu, a0.x, d);
            a0.y += __shfl_xor_sync(0xffffffffu, a0.y, d);
            a0.z += __shfl_xor_sync(0xffffffffu, a0.z, d);
            a0.w += __shfl_xor_sync(0xffffffffu, a0.w, d);
            a1.x += __shfl_xor_sync(0xffffffffu, a1.x, d);
            a1.y += __shfl_xor_sync(0xffffffffu, a1.y, d);
            a1.z += __shfl_xor_sync(0xffffffffu, a1.z, d);
            a1.w += __shfl_xor_sync(0xffffffffu, a1.w, d);
        }
        {
            float4 sv0 = g4[((h << 9) + nl0) * 8 + c]; ACC4(a0, sv0);
            float4 sv1 = g4[((h << 9) + nl1) * 8 + c]; ACC4(a1, sv1);
        }
        float dis0 = rsqrtf((float)(e0 - s0) + 1.0f);
        float dis1 = rsqrtf((float)(e1 - s1) + 1.0f);
        float4 bb = ((const float4*)sB)[c];
        a0.x = tanha(fmaf(dis0, a0.x, bb.x));
        a0.y = tanha(fmaf(dis0, a0.y, bb.y));
        a0.z = tanha(fmaf(dis0, a0.z, bb.z));
        a0.w = tanha(fmaf(dis0, a0.w, bb.w));
        a1.x = tanha(fmaf(dis1, a1.x, bb.x));
        a1.y = tanha(fmaf(dis1, a1.y, bb.y));
        a1.z = tanha(fmaf(dis1, a1.z, bb.z));
        a1.w = tanha(fmaf(dis1, a1.w, bb.w));
        float o0 = 0.0f, o1 = 0.0f;
        const float* wf = (const float*)wr;
#pragma unroll
        for (int kc = 0; kc < 8; kc++) {
            float u0 = __shfl_sync(0xffffffffu, a0.x, kc);
            float u1 = __shfl_sync(0xffffffffu, a1.x, kc);
            o0 = fmaf(u0, wf[4*kc+0], o0); o1 = fmaf(u1, wf[4*kc+0], o1);
            u0 = __shfl_sync(0xffffffffu, a0.y, kc);
            u1 = __shfl_sync(0xffffffffu, a1.y, kc);
            o0 = fmaf(u0, wf[4*kc+1], o0); o1 = fmaf(u1, wf[4*kc+1], o1);
            u0 = __shfl_sync(0xffffffffu, a0.z, kc);
            u1 = __shfl_sync(0xffffffffu, a1.z, kc);
            o0 = fmaf(u0, wf[4*kc+2], o0); o1 = fmaf(u1, wf[4*kc+2], o1);
            u0 = __shfl_sync(0xffffffffu, a0.w, kc);
            u1 = __shfl_sync(0xffffffffu, a1.w, kc);
            o0 = fmaf(u0, wf[4*kc+3], o0); o1 = fmaf(u1, wf[4*kc+3], o1);
        }
        outBase[(size_t)nl0 * HH + lane] = o0 * dis0;
        outBase[(size_t)nl1 * HH + lane] = o1 * dis1;
    }
}

// ---------------- C: layer-2 gather (packed f32x2) + Wl + pool partials ----------------
__global__ void __launch_bounds__(1024) k_C(const float* __restrict__ b2,
                                            const float* __restrict__ Wl,
                                            const float* __restrict__ bl) {
    extern __shared__ char smC[];
    float* sG = (float*)smC;
    int*   sRp = (int*)(smC + PP * HH * 4);
    unsigned short* sCsr = (unsigned short*)(sRp + 516);
    float* sB = (float*)(sCsr + HSTRIDE);
    float* sRed = sB + 32;
    int t = threadIdx.x;
    int g = blockIdx.x >> 1, h = blockIdx.x & 1, half = blockIdx.x;

    const float4* gs = (const float4*)(d_G2 + (size_t)g * PP * HH);
    float4* sg4 = (float4*)sG;
    for (int i = t; i < PP * HH / 4; i += 1024) sg4[i] = gs[i];
    if (t < 513) sRp[t] = d_rpH[half * 513 + t];
    if (t >= 992) sB[t - 992] = b2[t - 992];
    __syncthreads();
    int m = sRp[512];
    const unsigned int* gcsr = (const unsigned int*)(d_csrU + (size_t)half * HSTRIDE);
    unsigned int* scsr = (unsigned int*)sCsr;
    for (int i = t; i < (m + 1) / 2; i += 1024) scsr[i] = gcsr[i];

    int lane = t & 31, w = t >> 5;
    int c = lane & 7, g3 = lane >> 3;
    float4 wr[8];
    const float4* w4 = (const float4*)(Wl + lane * HH);
#pragma unroll
    for (int q = 0; q < 8; q++) wr[q] = w4[q];
    float blr = bl[lane];
    unsigned int sGa = (unsigned int)__cvta_generic_to_shared(sG) + (c << 4);
    __syncthreads();

    const float4* g4 = (const float4*)sG;
    float vsum = 0.0f;
    for (int nn = 0; nn < 16; nn += 2) {
        int nl0 = w * 16 + nn, nl1 = nl0 + 1;
        int s0 = sRp[nl0], e0 = sRp[nl0 + 1];
        int s1 = e0,        e1 = sRp[nl1 + 1];
        unsigned long long a0l = 0, a0h = 0, a1l = 0, a1h = 0;
        int p0 = s0, p1 = s1;
        for (; p0 + 32 <= e0 && p1 + 32 <= e1; p0 += 32, p1 += 32) {
#pragma unroll
            for (int i = 0; i < 4; i++) {
                int i0a = (int)sCsr[p0 + (2*i)   * 4 + g3];
                int i0b = (int)sCsr[p0 + (2*i+1) * 4 + g3];
                int i1a = (int)sCsr[p1 + (2*i)   * 4 + g3];
                int i1b = (int)sCsr[p1 + (2*i+1) * 4 + g3];
                ldsAdd(a0l, a0h, sGa + (i0a << 7));
                ldsAdd(a1l, a1h, sGa + (i1a << 7));
                ldsAdd(a0l, a0h, sGa + (i0b << 7));
                ldsAdd(a1l, a1h, sGa + (i1b << 7));
            }
        }
        for (; p0 + 32 <= e0; p0 += 32) {
#pragma unroll
            for (int i = 0; i < 8; i++) {
                int s = (int)sCsr[p0 + i * 4 + g3];
                ldsAdd(a0l, a0h, sGa + (s << 7));
            }
        }
        for (int j = p0 + g3; j < e0; j += 4) {
            int s = (int)sCsr[j];
            ldsAdd(a0l, a0h, sGa + (s << 7));
        }
        for (; p1 + 32 <= e1; p1 += 32) {
#pragma unroll
            for (int i = 0; i < 8; i++) {
                int s = (int)sCsr[p1 + i * 4 + g3];
                ldsAdd(a1l, a1h, sGa + (s << 7));
            }
        }
        for (int j = p1 + g3; j < e1; j += 4) {
            int s = (int)sCsr[j];
            ldsAdd(a1l, a1h, sGa + (s << 7));
        }
        float4 a0, a1;
        UNPACK2(a0l, a0.x, a0.y); UNPACK2(a0h, a0.z, a0.w);
        UNPACK2(a1l, a1.x, a1.y); UNPACK2(a1h, a1.z, a1.w);
#pragma unroll
        for (int d = 8; d <= 16; d <<= 1) {
            a0.x += __shfl_xor_sync(0xffffffffu, a0.x, d);
            a0.y += __shfl_xor_sync(0xffffffffu, a0.y, d);
            a0.z += __shfl_xor_sync(0xffffffffu, a0.z, d);
            a0.w += __shfl_xor_sync(0xffffffffu, a0.w, d);
            a1.x += __shfl_xor_sync(0xffffffffu, a1.x, d);
            a1.y += __shfl_xor_sync(0xffffffffu, a1.y, d);
            a1.z += __shfl_xor_sync(0xffffffffu, a1.z, d);
            a1.w += __shfl_xor_sync(0xffffffffu, a1.w, d);
        }
        {
            float4 sv0 = g4[((h << 9) + nl0) * 8 + c]; ACC4(a0, sv0);
            float4 sv1 = g4[((h << 9) + nl1) * 8 + c]; ACC4(a1, sv1);
        }
        float dis0 = rsqrtf((float)(e0 - s0) + 1.0f);
        float dis1 = rsqrtf((float)(e1 - s1) + 1.0f);
        float4 bb = ((const float4*)sB)[c];
        a0.x = tanha(fmaf(dis0, a0.x, bb.x));
        a0.y = tanha(fmaf(dis0, a0.y, bb.y));
        a0.z = tanha(fmaf(dis0, a0.z, bb.z));
        a0.w = tanha(fmaf(dis0, a0.w, bb.w));
        a1.x = tanha(fmaf(dis1, a1.x, bb.x));
        a1.y = tanha(fmaf(dis1, a1.y, bb.y));
        a1.z = tanha(fmaf(dis1, a1.z, bb.z));
        a1.w = tanha(fmaf(dis1, a1.w, bb.w));
        float o0 = blr, o1 = blr;
        const float* wf = (const float*)wr;
#pragma unroll
        for (int kc = 0; kc < 8; kc++) {
            float u0 = __shfl_sync(0xffffffffu, a0.x, kc);
            float u1 = __shfl_sync(0xffffffffu, a1.x, kc);
            o0 = fmaf(u0, wf[4*kc+0], o0); o1 = fmaf(u1, wf[4*kc+0], o1);
            u0 = __shfl_sync(0xffffffffu, a0.y, kc);
            u1 = __shfl_sync(0xffffffffu, a1.y, kc);
            o0 = fmaf(u0, wf[4*kc+1], o0); o1 = fmaf(u1, wf[4*kc+1], o1);
            u0 = __shfl_sync(0xffffffffu, a0.z, kc);
            u1 = __shfl_sync(0xffffffffu, a1.z, kc);
            o0 = fmaf(u0, wf[4*kc+2], o0); o1 = fmaf(u1, wf[4*kc+2], o1);
            u0 = __shfl_sync(0xffffffffu, a0.w, kc);
            u1 = __shfl_sync(0xffffffffu, a1.w, kc);
            o0 = fmaf(u0, wf[4*kc+3], o0); o1 = fmaf(u1, wf[4*kc+3], o1);
        }
        vsum += tanha(o0) + tanha(o1);
    }
    sRed[w * HH + lane] = vsum;
    __syncthreads();
    if (t < HH) {
        float s = 0.0f;
#pragma unroll
        for (int r = 0; r < 32; r++) s += sRed[r * HH + t];
        d_poolP[half * HH + t] = s;
    }
}

// ---------------- heads (full precision) ----------------
__global__ void k_head(const float* __restrict__ share,
                       const float* __restrict__ Wp, const float* __restrict__ bp,
                       const float* __restrict__ Vw1, const float* __restrict__ Vb1,
                       const float* __restrict__ Vw2, const float* __restrict__ Vb2,
                       const float* __restrict__ Vw3, const float* __restrict__ Vb3,
                       const float* __restrict__ Cw1, const float* __restrict__ Cb1,
                       const float* __restrict__ Cw2, const float* __restrict__ Cb2,
                       float* __restrict__ out) {
    int b = threadIdx.x;
    if (b >= BB) return;
    float p[HH];
#pragma unroll
    for (int k = 0; k < HH; k++)
        p[k] = d_poolP[(2*b) * HH + k] + d_poolP[(2*b+1) * HH + k];
    float h1[HH];
#pragma unroll
    for (int j = 0; j < HH; j++) {
        float a = bp[j];
#pragma unroll
        for (int k = 0; k < HH; k++) a = fmaf(p[k], Wp[j * HH + k], a);
        h1[j] = a;
    }
    float s[2 * HH];
#pragma unroll
    for (int k = 0; k < 2 * HH; k++) s[k] = share[b * 2 * HH + k];
    float a1[HH];
#pragma unroll
    for (int j = 0; j < HH; j++) {
        float a = Vb1[j];
#pragma unroll
        for (int k = 0; k < 2 * HH; k++) a = fmaf(s[k], Vw1[j * 2 * HH + k], a);
        a1[j] = tanhf(a);
    }
    float a2[HH];
#pragma unroll
    for (int j = 0; j < HH; j++) {
        float a = Vb2[j];
#pragma unroll
        for (int k = 0; k < HH; k++) a = fmaf(a1[k], Vw2[j * HH + k], a);
        a2[j] = tanhf(a);
    }
    float h2[HH];
#pragma unroll
    for (int j = 0; j < HH; j++) {
        float a = Vb3[j];
#pragma unroll
        for (int k = 0; k < HH; k++) a = fmaf(a2[k], Vw3[j * HH + k], a);
        h2[j] = a;
    }
    float val = Cb2[0];
#pragma unroll
    for (int j = 0; j < HH; j++) {
        float a = Cb1[j];
#pragma unroll
        for (int k = 0; k < HH; k++) a = fmaf(h1[k], Cw1[j * 2 * HH + k], a);
#pragma unroll
        for (int k = 0; k < HH; k++) a = fmaf(h2[k], Cw1[j * 2 * HH + HH + k], a);
        val = fmaf(tanhf(a), Cw2[j], val);
    }
    out[b] = val;
}

extern "C" void kernel_launch(void* const* d_in, const int* in_sizes, int n_in,
                              void* d_out, int out_size) {
    const float* x     = (const float*)d_in[0];
    const int*   ei    = (const int*)  d_in[1];
    const float* share = (const float*)d_in[3];
    const float* W1  = (const float*)d_in[4];
    const float* b1  = (const float*)d_in[5];
    const float* W2  = (const float*)d_in[6];
    const float* b2  = (const float*)d_in[7];
    const float* Wl  = (const float*)d_in[8];
    const float* bl  = (const float*)d_in[9];
    const float* Wp  = (const float*)d_in[10];
    const float* bp  = (const float*)d_in[11];
    const float* Vw1 = (const float*)d_in[12];
    const float* Vb1 = (const float*)d_in[13];
    const float* Vw2 = (const float*)d_in[14];
    const float* Vb2 = (const float*)d_in[15];
    const float* Vw3 = (const float*)d_in[16];
    const float* Vb3 = (const float*)d_in[17];
    const float* Cw1 = (const float*)d_in[18];
    const float* Cb1 = (const float*)d_in[19];
    const float* Cw2 = (const float*)d_in[20];
    const float* Cb2 = (const float*)d_in[21];

    int e = in_sizes[1] / 2;
    const int* src = ei;
    const int* dst = ei + e;

    int smA = 512 * 4 + 516 * 4 + HSTRIDE * 2 + HH * DIN * 4;      // ~43KB
    int smB = PP * HH * 4 + 516 * 4 + HSTRIDE * 2 + 32 * 4;        // ~170KB
    int smC = smB + 32 * HH * 4;                                   // ~174KB

    cudaFuncSetAttribute(k_A, cudaFuncAttributeMaxDynamicSharedMemorySize, smA);
    cudaFuncSetAttribute(k_B, cudaFuncAttributeMaxDynamicSharedMemorySize, smB);
    cudaFuncSetAttribute(k_C, cudaFuncAttributeMaxDynamicSharedMemorySize, smC);

    k_z   <<<1, 64>>>();
    k_bin <<<BCTA, 256>>>(src, dst);
    k_A   <<<128, 1024, smA>>>(x, W1);
    k_B   <<<128, 1024, smB>>>(b1, W2);
    k_C   <<<128, 1024, smC>>>(b2, Wl, bl);
    k_head<<<1, 64>>>(share, Wp, bp, Vw1, Vb1, Vw2, Vb2, Vw3, Vb3,
                      Cw1, Cb1, Cw2, Cb2, (float*)d_out);
}